// round 13
// baseline (speedup 1.0000x reference)
#include <cuda_runtime.h>
#include <cuda_bf16.h>
#include <math.h>
#include <stdint.h>

#define N_NODES 50000
#define N_EDGES 800000
#define D_IN    128
#define D1      150
#define D2      100
#define D_OUT   64

#define KP1 128   // gemm1 K
#define N1  160   // gemm1 N padded (150->160)
#define H1S 160   // h1 bf16 stride = gemm2 K (150->160)
#define KP2 160
#define N2  224   // gemm2 N: [Wn pad 112 | Ws pad 112]
#define PS  112   // p/s fp32 stride
#define H2S 112   // h2 bf16 stride = gemm3 K (100->112)
#define KP3 112
#define N3  64

#define SMS 24    // smem row stride in bf16 (48B: conflict-free LDSM phases)
#define STAGES 4  // cp.async pipeline depth

// ---------------- scratch (device globals) -----------------------------------
__device__ int   g_deg_out_i[N_NODES];
__device__ int   g_deg_in_i [N_NODES];
__device__ int   g_rowoff[N_NODES];
__device__ int   g_fill  [N_NODES];
__device__ int   g_total;
__device__ int   g_csr[N_EDGES];
__device__ float g_norm_out[N_NODES];

__device__ __nv_bfloat16 g_aggh[(size_t)N_NODES * KP1];
__device__ __nv_bfloat16 g_aggl[(size_t)N_NODES * KP1];
__device__ __nv_bfloat16 g_h1h [(size_t)N_NODES * H1S];
__device__ __nv_bfloat16 g_h1l [(size_t)N_NODES * H1S];
__device__ float         g_pf  [(size_t)N_NODES * PS];
__device__ float         g_sf  [(size_t)N_NODES * PS];
__device__ __nv_bfloat16 g_h2h [(size_t)N_NODES * H2S];
__device__ __nv_bfloat16 g_h2l [(size_t)N_NODES * H2S];

__device__ __nv_bfloat16 g_w1h[N1 * KP1];   // W^T [n][k] hi/lo splits
__device__ __nv_bfloat16 g_w1l[N1 * KP1];
__device__ __nv_bfloat16 g_w2h[N2 * KP2];
__device__ __nv_bfloat16 g_w2l[N2 * KP2];
__device__ __nv_bfloat16 g_w3h[N3 * KP3];
__device__ __nv_bfloat16 g_w3l[N3 * KP3];
__device__ float g_b1p[N1];

__device__ __forceinline__ float elu(float v) { return v > 0.f ? v : expm1f(v); }

__device__ __forceinline__ void bfsplit(float v, __nv_bfloat16& h, __nv_bfloat16& l) {
    h = __float2bfloat16(v);
    l = __float2bfloat16(v - __bfloat162float(h));
}

__device__ __forceinline__ uint32_t smem_u32(const void* p) {
    uint32_t a;
    asm("{ .reg .u64 t; cvta.to.shared.u64 t, %1; cvt.u32.u64 %0, t; }" : "=r"(a) : "l"(p));
    return a;
}

// ---------------- HMMA m16n8k16 bf16 -> f32 ----------------------------------
__device__ __forceinline__ void mma16816(float* c, const uint32_t* a, const uint32_t* b) {
    asm volatile(
        "mma.sync.aligned.m16n8k16.row.col.f32.bf16.bf16.f32 "
        "{%0,%1,%2,%3}, {%4,%5,%6,%7}, {%8,%9}, {%0,%1,%2,%3};"
        : "+f"(c[0]), "+f"(c[1]), "+f"(c[2]), "+f"(c[3])
        : "r"(a[0]), "r"(a[1]), "r"(a[2]), "r"(a[3]), "r"(b[0]), "r"(b[1]));
}

__device__ __forceinline__ void ldsm4(uint32_t* r, uint32_t saddr) {
    asm volatile("ldmatrix.sync.aligned.m8n8.x4.shared.b16 {%0,%1,%2,%3}, [%4];"
                 : "=r"(r[0]), "=r"(r[1]), "=r"(r[2]), "=r"(r[3]) : "r"(saddr));
}

__device__ __forceinline__ void cp16(uint32_t sa, const void* gp, int ssz) {
    asm volatile("cp.async.cg.shared.global [%0], [%1], 16, %2;"
                 :: "r"(sa), "l"(gp), "r"(ssz) : "memory");
}

// ---------------- fused hi/lo HMMA mainloop, cp.async pipelined --------------
// block: 256 thr = 8 M-warps (128 rows); tile 128 x NCOLS
// stage layout (rows x SMS bf16): [Ah:128 | Al:128 | Bh:NCOLS | Bl:NCOLS]
template<int NT, int KS, int KPA, int KPB, int NCOLS>
__device__ __forceinline__ void hmma_tiles(
    const __nv_bfloat16* __restrict__ Ah, const __nv_bfloat16* __restrict__ Al,
    const __nv_bfloat16* __restrict__ Bh, const __nv_bfloat16* __restrict__ Bl,
    int row0, int cb, __nv_bfloat16* sm, float (*acc)[4])
{
    const int tid = threadIdx.x;
    const int wid = tid >> 5, lane = tid & 31;
    constexpr int BUFROWS = 256 + 2 * NCOLS;
    constexpr int AU4 = 512;              // 128 rows x 2 halves x 2 arrays
    constexpr int BU4 = 4 * NCOLS;

    const int at = lane >> 3;
    const int arow = wid * 16 + (at & 1) * 8 + (lane & 7);
    const int akoff = (at >> 1) * 8;
    const int brow0 = (at >> 1) * 8 + (lane & 7);
    const int bkoff = (at & 1) * 8;

#define ISSUE_CHUNK(it_) do {                                                        \
        if ((it_) < KS) {                                                            \
            int ks_ = (it_);                                                         \
            __nv_bfloat16* dst_ = sm + ((it_) % STAGES) * BUFROWS * SMS;             \
            for (int idx = tid; idx < AU4 + BU4; idx += 256) {                       \
                if (idx < AU4) {                                                     \
                    int arr_ = idx >> 8, r_ = (idx >> 1) & 127, h_ = idx & 1;        \
                    const __nv_bfloat16* s_ = arr_ ? Al : Ah;                        \
                    int gr_ = row0 + r_; int ssz_ = 16;                              \
                    if (gr_ >= N_NODES) { gr_ = N_NODES - 1; ssz_ = 0; }             \
                    cp16(smem_u32(dst_ + (arr_ * 128 + r_) * SMS + h_ * 8),          \
                         s_ + (size_t)gr_ * KPA + ks_ * 16 + h_ * 8, ssz_);          \
                } else {                                                             \
                    int j_ = idx - AU4;                                              \
                    int arr_ = j_ / (2 * NCOLS), n_ = (j_ >> 1) % NCOLS, h_ = j_ & 1;\
                    const __nv_bfloat16* s_ = arr_ ? Bl : Bh;                        \
                    cp16(smem_u32(dst_ + (256 + arr_ * NCOLS + n_) * SMS + h_ * 8),  \
                         s_ + (size_t)(cb + n_) * KPB + ks_ * 16 + h_ * 8, 16);      \
                }                                                                    \
            }                                                                        \
        }                                                                            \
        asm volatile("cp.async.commit_group;" ::: "memory");                         \
    } while (0)

#pragma unroll
    for (int s = 0; s < STAGES - 1; s++) ISSUE_CHUNK(s);

    for (int it = 0; it < KS; it++) {
        asm volatile("cp.async.wait_group %0;" :: "n"(STAGES - 2));
        __syncthreads();
        ISSUE_CHUNK(it + STAGES - 1);
        uint32_t base = smem_u32(sm + (it % STAGES) * BUFROWS * SMS);
        uint32_t aHaddr = base + (uint32_t)(arow * SMS + akoff) * 2;
        uint32_t aH[4], aL[4];
        ldsm4(aH, aHaddr);
        ldsm4(aL, aHaddr + 128 * SMS * 2);
        uint32_t bbase = base + (uint32_t)((256 + brow0) * SMS + bkoff) * 2;
#pragma unroll
        for (int nt = 0; nt < NT; nt += 2) {
            uint32_t bH[4], bL[4];
            uint32_t baddr = bbase + (uint32_t)(nt * 8 * SMS) * 2;
            ldsm4(bH, baddr);
            ldsm4(bL, baddr + NCOLS * SMS * 2);
            mma16816(acc[nt],     aH, bH);
            mma16816(acc[nt + 1], aH, bH + 2);
            mma16816(acc[nt],     aL, bH);
            mma16816(acc[nt + 1], aL, bH + 2);
            mma16816(acc[nt],     aH, bL);
            mma16816(acc[nt + 1], aH, bL + 2);
        }
    }
    __syncthreads();
#undef ISSUE_CHUNK
}

// ---------------- weight prep + counter zero ---------------------------------
__global__ void prep_weights(const float* __restrict__ W1, const float* __restrict__ b1,
                             const float* __restrict__ Wn, const float* __restrict__ Ws,
                             const float* __restrict__ W3) {
    int stride = gridDim.x * blockDim.x;
    int t0 = blockIdx.x * blockDim.x + threadIdx.x;
    for (int i = t0; i < N1 * KP1; i += stride) {
        int n = i / KP1, k = i % KP1;
        float v = (n < D1) ? W1[k * D1 + n] : 0.f;
        bfsplit(v, g_w1h[i], g_w1l[i]);
    }
    for (int i = t0; i < N2 * KP2; i += stride) {
        int n = i / KP2, k = i % KP2;
        float v = 0.f;
        if (k < D1) {
            if (n < D2)                       v = Wn[k * D2 + n];
            else if (n >= PS && n < PS + D2)  v = Ws[k * D2 + (n - PS)];
        }
        bfsplit(v, g_w2h[i], g_w2l[i]);
    }
    for (int i = t0; i < N3 * KP3; i += stride) {
        int n = i / KP3, k = i % KP3;
        float v = (k < D2) ? W3[k * D_OUT + n] : 0.f;
        bfsplit(v, g_w3h[i], g_w3l[i]);
    }
    for (int i = t0; i < N1; i += stride) g_b1p[i] = (i < D1) ? b1[i] : 0.f;
    for (int i = t0; i < N_NODES; i += stride) {
        g_deg_out_i[i] = 0;
        g_deg_in_i[i]  = 0;
    }
    if (t0 == 0) g_total = 0;
}

// ---------------- degrees ----------------------------------------------------
__global__ void degree_kernel(const int* __restrict__ src, const int* __restrict__ dst) {
    int i = blockIdx.x * blockDim.x + threadIdx.x;
    if (i < N_EDGES) {
        atomicAdd(&g_deg_out_i[src[i]], 1);
        atomicAdd(&g_deg_in_i [dst[i]], 1);
    }
}

// ---------------- row offsets via warp-aggregated atomic ---------------------
__global__ void rowoff_kernel() {
    int i = blockIdx.x * blockDim.x + threadIdx.x;
    int lane = threadIdx.x & 31;
    int d = (i < N_NODES) ? g_deg_in_i[i] : 0;
    int x = d;
#pragma unroll
    for (int off = 1; off < 32; off <<= 1) {
        int t = __shfl_up_sync(0xffffffffu, x, off);
        if (lane >= off) x += t;
    }
    int excl = x - d;
    int total = __shfl_sync(0xffffffffu, x, 31);
    int base = 0;
    if (lane == 0) base = atomicAdd(&g_total, total);
    base = __shfl_sync(0xffffffffu, base, 0);
    if (i < N_NODES) {
        int o = base + excl;
        g_rowoff[i] = o;
        g_fill[i]   = o;
        g_norm_out[i] = rsqrtf(fmaxf((float)g_deg_out_i[i], 1.f));
    }
}

__global__ void bucket_kernel(const int* __restrict__ src, const int* __restrict__ dst) {
    int i = blockIdx.x * blockDim.x + threadIdx.x;
    if (i < N_EDGES) {
        int pos = atomicAdd(&g_fill[dst[i]], 1);
        g_csr[pos] = src[i];
    }
}

// ---------------- gather 1 -> bf16 hi/lo split -------------------------------
__global__ void gather1_kernel(const float* __restrict__ x) {
    int w    = (blockIdx.x * blockDim.x + threadIdx.x) >> 5;
    int lane = threadIdx.x & 31;
    if (w >= N_NODES) return;
    int beg = g_rowoff[w];
    int cnt = g_deg_in_i[w];
    float4 acc = make_float4(0.f, 0.f, 0.f, 0.f);
    for (int base = 0; base < cnt; base += 32) {
        int idx = base + lane;
        int s = 0; float ns = 0.f;
        if (idx < cnt) { s = g_csr[beg + idx]; ns = g_norm_out[s]; }
        int m = min(32, cnt - base);
        for (int j = 0; j < m; j++) {
            int   sj  = __shfl_sync(0xffffffffu, s,  j);
            float nsj = __shfl_sync(0xffffffffu, ns, j);
            float4 v = __ldg((const float4*)(x + (size_t)sj * D_IN) + lane);
            acc.x = fmaf(v.x, nsj, acc.x);
            acc.y = fmaf(v.y, nsj, acc.y);
            acc.z = fmaf(v.z, nsj, acc.z);
            acc.w = fmaf(v.w, nsj, acc.w);
        }
    }
    float nin = rsqrtf(fmaxf((float)cnt, 1.f));
    float vv[4] = {acc.x * nin, acc.y * nin, acc.z * nin, acc.w * nin};
    __nv_bfloat16 h[4], l[4];
#pragma unroll
    for (int q = 0; q < 4; q++) bfsplit(vv[q], h[q], l[q]);
    __nv_bfloat162* ph = (__nv_bfloat162*)(g_aggh + (size_t)w * KP1 + lane * 4);
    __nv_bfloat162* pl = (__nv_bfloat162*)(g_aggl + (size_t)w * KP1 + lane * 4);
    ph[0] = __halves2bfloat162(h[0], h[1]);
    ph[1] = __halves2bfloat162(h[2], h[3]);
    pl[0] = __halves2bfloat162(l[0], l[1]);
    pl[1] = __halves2bfloat162(l[2], l[3]);
}

// ---------------- GEMM1 (HMMA): h1 = ELU(agg @ W1 + b1) -> bf16 split --------
// grid (391, 2): 128 rows x 80 cols per block
__global__ __launch_bounds__(256) void hmma_gemm1_kernel() {
    extern __shared__ __nv_bfloat16 sm[];
    int wid = threadIdx.x >> 5;
    int lane = threadIdx.x & 31;
    int gid = lane >> 2, tig = lane & 3;
    int row0 = blockIdx.x * 128;
    int cb = blockIdx.y * 80;
    float acc[10][4];
#pragma unroll
    for (int i = 0; i < 10; i++)
#pragma unroll
        for (int j = 0; j < 4; j++) acc[i][j] = 0.f;
    hmma_tiles<10, 8, KP1, KP1, 80>(g_aggh, g_aggl, g_w1h, g_w1l, row0, cb, sm, acc);
    int r0 = row0 + wid * 16 + gid, r1 = r0 + 8;
#pragma unroll
    for (int nt = 0; nt < 10; nt++) {
        int c = cb + nt * 8 + tig * 2;
        float bb0 = g_b1p[c], bb1 = g_b1p[c + 1];
        if (r0 < N_NODES) {
            float x0 = elu(acc[nt][0] + bb0), x1 = elu(acc[nt][1] + bb1);
            __nv_bfloat16 h0, l0, h1, l1;
            bfsplit(x0, h0, l0); bfsplit(x1, h1, l1);
            *(__nv_bfloat162*)(g_h1h + (size_t)r0 * H1S + c) = __halves2bfloat162(h0, h1);
            *(__nv_bfloat162*)(g_h1l + (size_t)r0 * H1S + c) = __halves2bfloat162(l0, l1);
        }
        if (r1 < N_NODES) {
            float x0 = elu(acc[nt][2] + bb0), x1 = elu(acc[nt][3] + bb1);
            __nv_bfloat16 h0, l0, h1, l1;
            bfsplit(x0, h0, l0); bfsplit(x1, h1, l1);
            *(__nv_bfloat162*)(g_h1h + (size_t)r1 * H1S + c) = __halves2bfloat162(h0, h1);
            *(__nv_bfloat162*)(g_h1l + (size_t)r1 * H1S + c) = __halves2bfloat162(l0, l1);
        }
    }
}

// ---------------- GEMM2 (HMMA): [p|s] = h1 @ [Wn|Ws] -> fp32 -----------------
// grid (391, 2): 128 rows x 112 cols; y==0 -> p, y==1 -> s
__global__ __launch_bounds__(256) void hmma_gemm2_kernel() {
    extern __shared__ __nv_bfloat16 sm[];
    int wid = threadIdx.x >> 5;
    int lane = threadIdx.x & 31;
    int gid = lane >> 2, tig = lane & 3;
    int row0 = blockIdx.x * 128;
    int cb = blockIdx.y * 112;
    float acc[14][4];
#pragma unroll
    for (int i = 0; i < 14; i++)
#pragma unroll
        for (int j = 0; j < 4; j++) acc[i][j] = 0.f;
    hmma_tiles<14, 10, KP2, KP2, 112>(g_h1h, g_h1l, g_w2h, g_w2l, row0, cb, sm, acc);
    int r0 = row0 + wid * 16 + gid, r1 = r0 + 8;
    float* base = (blockIdx.y == 0) ? g_pf : g_sf;
#pragma unroll
    for (int nt = 0; nt < 14; nt++) {
        int c = nt * 8 + tig * 2;
        if (r0 < N_NODES) {
            float2 v; v.x = acc[nt][0]; v.y = acc[nt][1];
            *(float2*)(base + (size_t)r0 * PS + c) = v;
        }
        if (r1 < N_NODES) {
            float2 v; v.x = acc[nt][2]; v.y = acc[nt][3];
            *(float2*)(base + (size_t)r1 * PS + c) = v;
        }
    }
}

// ---------------- gather 2 + SAGE epilogue -> h2 bf16 split ------------------
__global__ void gather2_kernel(const float* __restrict__ b2) {
    int w    = (blockIdx.x * blockDim.x + threadIdx.x) >> 5;
    int lane = threadIdx.x & 31;
    if (w >= N_NODES) return;
    int beg = g_rowoff[w];
    int cnt = g_deg_in_i[w];
    bool act = lane < (D2 / 4);   // 25 data lanes
    float4 acc = make_float4(0.f, 0.f, 0.f, 0.f);
    for (int base = 0; base < cnt; base += 32) {
        int idx = base + lane;
        int s = (idx < cnt) ? g_csr[beg + idx] : 0;
        int m = min(32, cnt - base);
        for (int j = 0; j < m; j++) {
            int sj = __shfl_sync(0xffffffffu, s, j);
            if (act) {
                float4 v = __ldg((const float4*)(g_pf + (size_t)sj * PS) + lane);
                acc.x += v.x; acc.y += v.y; acc.z += v.z; acc.w += v.w;
            }
        }
    }
    float o[4] = {0.f, 0.f, 0.f, 0.f};
    if (act) {
        float invd = 1.f / fmaxf((float)cnt, 1.f);
        float4 sv = *(const float4*)(g_sf + (size_t)w * PS + lane * 4);
        float4 bv = *(const float4*)(b2 + lane * 4);
        o[0] = elu(acc.x * invd + sv.x + bv.x);
        o[1] = elu(acc.y * invd + sv.y + bv.y);
        o[2] = elu(acc.z * invd + sv.z + bv.z);
        o[3] = elu(acc.w * invd + sv.w + bv.w);
    }
    if (lane < H2S / 4) {   // 28 lanes cover 112 cols (zeros beyond col 100)
        __nv_bfloat16 h[4], l[4];
#pragma unroll
        for (int q = 0; q < 4; q++) bfsplit(o[q], h[q], l[q]);
        __nv_bfloat162* ph = (__nv_bfloat162*)(g_h2h + (size_t)w * H2S + lane * 4);
        __nv_bfloat162* pl = (__nv_bfloat162*)(g_h2l + (size_t)w * H2S + lane * 4);
        ph[0] = __halves2bfloat162(h[0], h[1]);
        ph[1] = __halves2bfloat162(h[2], h[3]);
        pl[0] = __halves2bfloat162(l[0], l[1]);
        pl[1] = __halves2bfloat162(l[2], l[3]);
    }
}

// ---------------- GEMM3 (HMMA): out = ELU(h2 @ W3 + b3) ----------------------
// grid (391): 128 rows x 64 cols
__global__ __launch_bounds__(256) void hmma_gemm3_kernel(const float* __restrict__ b3,
                                                         float* __restrict__ out) {
    extern __shared__ __nv_bfloat16 sm[];
    int wid = threadIdx.x >> 5;
    int lane = threadIdx.x & 31;
    int gid = lane >> 2, tig = lane & 3;
    int row0 = blockIdx.x * 128;
    float acc[8][4];
#pragma unroll
    for (int i = 0; i < 8; i++)
#pragma unroll
        for (int j = 0; j < 4; j++) acc[i][j] = 0.f;
    hmma_tiles<8, 7, KP3, KP3, 64>(g_h2h, g_h2l, g_w3h, g_w3l, row0, 0, sm, acc);
    int r0 = row0 + wid * 16 + gid, r1 = r0 + 8;
#pragma unroll
    for (int nt = 0; nt < 8; nt++) {
        int c = nt * 8 + tig * 2;
        float bb0 = b3[c], bb1 = b3[c + 1];
        if (r0 < N_NODES) {
            float2 v;
            v.x = elu(acc[nt][0] + bb0);
            v.y = elu(acc[nt][1] + bb1);
            *(float2*)(out + (size_t)r0 * D_OUT + c) = v;
        }
        if (r1 < N_NODES) {
            float2 v;
            v.x = elu(acc[nt][2] + bb0);
            v.y = elu(acc[nt][3] + bb1);
            *(float2*)(out + (size_t)r1 * D_OUT + c) = v;
        }
    }
}

// ---------------- launch -----------------------------------------------------
extern "C" void kernel_launch(void* const* d_in, const int* in_sizes, int n_in,
                              void* d_out, int out_size) {
    const float* x   = (const float*)d_in[0];
    const int*   src = (const int*)d_in[1];
    const int*   dst = (const int*)d_in[2];
    const float* W1  = (const float*)d_in[3];
    const float* b1  = (const float*)d_in[4];
    const float* Wn  = (const float*)d_in[5];
    const float* Ws  = (const float*)d_in[6];
    const float* b2  = (const float*)d_in[7];
    const float* W3  = (const float*)d_in[8];
    const float* b3  = (const float*)d_in[9];
    float* out = (float*)d_out;

    const int EDGE_BLOCKS = (N_EDGES + 255) / 256;      // 3125
    const int WARP_BLOCKS = (N_NODES * 32 + 255) / 256; // 6250
    const int MMA_BLOCKS  = (N_NODES + 127) / 128;      // 391

    const int SM1 = STAGES * (256 + 2 * 80)  * SMS * 2; // 79872 B
    const int SM2 = STAGES * (256 + 2 * 112) * SMS * 2; // 92160 B
    const int SM3 = STAGES * (256 + 2 * 64)  * SMS * 2; // 73728 B

    cudaFuncSetAttribute(hmma_gemm1_kernel, cudaFuncAttributeMaxDynamicSharedMemorySize, SM1);
    cudaFuncSetAttribute(hmma_gemm2_kernel, cudaFuncAttributeMaxDynamicSharedMemorySize, SM2);
    cudaFuncSetAttribute(hmma_gemm3_kernel, cudaFuncAttributeMaxDynamicSharedMemorySize, SM3);

    prep_weights<<<160, 256>>>(W1, b1, Wn, Ws, W3);
    degree_kernel<<<EDGE_BLOCKS, 256>>>(src, dst);
    rowoff_kernel<<<(N_NODES + 255) / 256, 256>>>();
    bucket_kernel<<<EDGE_BLOCKS, 256>>>(src, dst);
    gather1_kernel<<<WARP_BLOCKS, 256>>>(x);
    hmma_gemm1_kernel<<<dim3(MMA_BLOCKS, 2), 256, SM1>>>();
    hmma_gemm2_kernel<<<dim3(MMA_BLOCKS, 2), 256, SM2>>>();
    gather2_kernel<<<WARP_BLOCKS, 256>>>(b2);
    hmma_gemm3_kernel<<<MMA_BLOCKS, 256, SM3>>>(b3, out);
}

// round 14
// speedup vs baseline: 1.3170x; 1.3170x over previous
#include <cuda_runtime.h>
#include <cuda_bf16.h>
#include <math.h>
#include <stdint.h>

#define N_NODES 50000
#define N_EDGES 800000
#define D_IN    128
#define D1      150
#define D2      100
#define D_OUT   64

#define KP1 128   // gemm1 K
#define N1  160   // gemm1 N padded (150->160)
#define H1S 160   // h1 bf16 stride = gemm2 K (150->160)
#define KP2 160
#define N2  224   // gemm2 N: [Wn pad 112 | Ws pad 112]
#define PS  112   // p/s fp32 stride
#define H2S 112   // h2 bf16 stride = gemm3 K (100->112)
#define KP3 112
#define N3  64

#define SMS 24    // smem row stride in bf16 (48B: conflict-free LDSM phases)

// ---------------- scratch (device globals; statically zero-initialized) ------
// INVARIANT: g_deg_out_i / g_deg_in_i / g_total are zero at kernel_launch entry
// (static init on first call; gemm3 re-zeroes them at the end of every launch).
__device__ int   g_deg_out_i[N_NODES];
__device__ int   g_deg_in_i [N_NODES];
__device__ int   g_rowoff[N_NODES];
__device__ int   g_fill  [N_NODES];
__device__ int   g_total;
__device__ int   g_csr[N_EDGES];
__device__ float g_norm_out[N_NODES];
__device__ int   g_deg_save[N_NODES];   // deg_in copy surviving the re-zero

__device__ __nv_bfloat16 g_aggh[(size_t)N_NODES * KP1];
__device__ __nv_bfloat16 g_aggl[(size_t)N_NODES * KP1];
__device__ __nv_bfloat16 g_h1h [(size_t)N_NODES * H1S];
__device__ __nv_bfloat16 g_h1l [(size_t)N_NODES * H1S];
__device__ float         g_pf  [(size_t)N_NODES * PS];
__device__ float         g_sf  [(size_t)N_NODES * PS];
__device__ __nv_bfloat16 g_h2h [(size_t)N_NODES * H2S];
__device__ __nv_bfloat16 g_h2l [(size_t)N_NODES * H2S];

__device__ __nv_bfloat16 g_w1h[N1 * KP1];   // W^T [n][k] hi/lo splits
__device__ __nv_bfloat16 g_w1l[N1 * KP1];
__device__ __nv_bfloat16 g_w2h[N2 * KP2];
__device__ __nv_bfloat16 g_w2l[N2 * KP2];
__device__ __nv_bfloat16 g_w3h[N3 * KP3];
__device__ __nv_bfloat16 g_w3l[N3 * KP3];
__device__ float g_b1p[N1];

__device__ __forceinline__ float elu(float v) { return v > 0.f ? v : expm1f(v); }

__device__ __forceinline__ void bfsplit(float v, __nv_bfloat16& h, __nv_bfloat16& l) {
    h = __float2bfloat16(v);
    l = __float2bfloat16(v - __bfloat162float(h));
}

__device__ __forceinline__ uint32_t smem_u32(const void* p) {
    uint32_t a;
    asm("{ .reg .u64 t; cvta.to.shared.u64 t, %1; cvt.u32.u64 %0, t; }" : "=r"(a) : "l"(p));
    return a;
}

// ---------------- HMMA m16n8k16 bf16 -> f32 ----------------------------------
__device__ __forceinline__ void mma16816(float* c, const uint32_t* a, const uint32_t* b) {
    asm volatile(
        "mma.sync.aligned.m16n8k16.row.col.f32.bf16.bf16.f32 "
        "{%0,%1,%2,%3}, {%4,%5,%6,%7}, {%8,%9}, {%0,%1,%2,%3};"
        : "+f"(c[0]), "+f"(c[1]), "+f"(c[2]), "+f"(c[3])
        : "r"(a[0]), "r"(a[1]), "r"(a[2]), "r"(a[3]), "r"(b[0]), "r"(b[1]));
}

__device__ __forceinline__ void ldsm4(uint32_t* r, uint32_t saddr) {
    asm volatile("ldmatrix.sync.aligned.m8n8.x4.shared.b16 {%0,%1,%2,%3}, [%4];"
                 : "=r"(r[0]), "=r"(r[1]), "=r"(r[2]), "=r"(r[3]) : "r"(saddr));
}

// ---------------- fused hi/lo HMMA mainloop (R12-proven) ---------------------
// block: 256 thr = 8 M-warps (128 rows); tile 128 x NCOLS
// buffer layout (rows x SMS bf16): [Ah:128 | Al:128 | Bh:NCOLS | Bl:NCOLS]
template<int NT, int KS, int KPA, int KPB, int NCOLS>
__device__ __forceinline__ void hmma_tiles(
    const __nv_bfloat16* __restrict__ Ah, const __nv_bfloat16* __restrict__ Al,
    const __nv_bfloat16* __restrict__ Bh, const __nv_bfloat16* __restrict__ Bl,
    int row0, int cb, __nv_bfloat16* sm, float (*acc)[4])
{
    const int tid = threadIdx.x;
    const int wid = tid >> 5, lane = tid & 31;
    constexpr int BUFROWS = 256 + 2 * NCOLS;
    constexpr int AU4 = 512;              // 128 rows x 2 halves x 2 arrays
    constexpr int BU4 = 4 * NCOLS;

    const int at = lane >> 3;
    const int arow = wid * 16 + (at & 1) * 8 + (lane & 7);
    const int akoff = (at >> 1) * 8;
    const int brow0 = (at >> 1) * 8 + (lane & 7);
    const int bkoff = (at & 1) * 8;

#define LOAD_CHUNK(it_) do {                                                         \
        int ks_ = (it_);                                                             \
        __nv_bfloat16* dst_ = sm + ((it_) & 1) * BUFROWS * SMS;                      \
        for (int idx = tid; idx < AU4 + BU4; idx += 256) {                           \
            if (idx < AU4) {                                                         \
                int arr_ = idx >> 8, r_ = (idx >> 1) & 127, h_ = idx & 1;            \
                const __nv_bfloat16* s_ = arr_ ? Al : Ah;                            \
                uint4 v_ = make_uint4(0u, 0u, 0u, 0u);                               \
                if (row0 + r_ < N_NODES)                                             \
                    v_ = *(const uint4*)(s_ + (size_t)(row0 + r_) * KPA + ks_ * 16 + h_ * 8); \
                *(uint4*)(dst_ + (arr_ * 128 + r_) * SMS + h_ * 8) = v_;             \
            } else {                                                                 \
                int j_ = idx - AU4;                                                  \
                int arr_ = j_ / (2 * NCOLS), n_ = (j_ >> 1) % NCOLS, h_ = j_ & 1;    \
                const __nv_bfloat16* s_ = arr_ ? Bl : Bh;                            \
                uint4 v_ = *(const uint4*)(s_ + (size_t)(cb + n_) * KPB + ks_ * 16 + h_ * 8); \
                *(uint4*)(dst_ + (256 + arr_ * NCOLS + n_) * SMS + h_ * 8) = v_;     \
            }                                                                        \
        }                                                                            \
    } while (0)

    LOAD_CHUNK(0);
    __syncthreads();
    for (int it = 0; it < KS; it++) {
        if (it + 1 < KS) LOAD_CHUNK(it + 1);
        uint32_t base = smem_u32(sm + (it & 1) * BUFROWS * SMS);
        uint32_t aHaddr = base + (uint32_t)(arow * SMS + akoff) * 2;
        uint32_t aH[4], aL[4];
        ldsm4(aH, aHaddr);
        ldsm4(aL, aHaddr + 128 * SMS * 2);
        uint32_t bbase = base + (uint32_t)((256 + brow0) * SMS + bkoff) * 2;
#pragma unroll
        for (int nt = 0; nt < NT; nt += 2) {
            uint32_t bH[4], bL[4];
            uint32_t baddr = bbase + (uint32_t)(nt * 8 * SMS) * 2;
            ldsm4(bH, baddr);
            ldsm4(bL, baddr + NCOLS * SMS * 2);
            mma16816(acc[nt],     aH, bH);
            mma16816(acc[nt + 1], aH, bH + 2);
            mma16816(acc[nt],     aL, bH);
            mma16816(acc[nt + 1], aL, bH + 2);
            mma16816(acc[nt],     aH, bL);
            mma16816(acc[nt + 1], aH, bL + 2);
        }
        __syncthreads();
    }
#undef LOAD_CHUNK
}

// ---------------- degrees (counters are zero on entry; see invariant) --------
__global__ void degree_kernel(const int* __restrict__ src, const int* __restrict__ dst) {
    int i = blockIdx.x * blockDim.x + threadIdx.x;
    if (i < N_EDGES) {
        atomicAdd(&g_deg_out_i[src[i]], 1);
        atomicAdd(&g_deg_in_i [dst[i]], 1);
    }
}

// ---------------- row offsets via warp-aggregated atomic ---------------------
__global__ void rowoff_kernel() {
    int i = blockIdx.x * blockDim.x + threadIdx.x;
    int lane = threadIdx.x & 31;
    int d = (i < N_NODES) ? g_deg_in_i[i] : 0;
    int x = d;
#pragma unroll
    for (int off = 1; off < 32; off <<= 1) {
        int t = __shfl_up_sync(0xffffffffu, x, off);
        if (lane >= off) x += t;
    }
    int excl = x - d;
    int total = __shfl_sync(0xffffffffu, x, 31);
    int base = 0;
    if (lane == 0) base = atomicAdd(&g_total, total);
    base = __shfl_sync(0xffffffffu, base, 0);
    if (i < N_NODES) {
        int o = base + excl;
        g_rowoff[i] = o;
        g_fill[i]   = o;
        g_deg_save[i] = d;
        g_norm_out[i] = rsqrtf(fmaxf((float)g_deg_out_i[i], 1.f));
    }
}

__global__ void bucket_kernel(const int* __restrict__ src, const int* __restrict__ dst) {
    int i = blockIdx.x * blockDim.x + threadIdx.x;
    if (i < N_EDGES) {
        int pos = atomicAdd(&g_fill[dst[i]], 1);
        g_csr[pos] = src[i];
    }
}

// ---------------- gather 1 -> bf16 hi/lo split -------------------------------
__global__ void gather1_kernel(const float* __restrict__ x) {
    int w    = (blockIdx.x * blockDim.x + threadIdx.x) >> 5;
    int lane = threadIdx.x & 31;
    if (w >= N_NODES) return;
    int beg = g_rowoff[w];
    int cnt = g_deg_save[w];
    float4 acc = make_float4(0.f, 0.f, 0.f, 0.f);
    for (int base = 0; base < cnt; base += 32) {
        int idx = base + lane;
        int s = 0; float ns = 0.f;
        if (idx < cnt) { s = g_csr[beg + idx]; ns = g_norm_out[s]; }
        int m = min(32, cnt - base);
        for (int j = 0; j < m; j++) {
            int   sj  = __shfl_sync(0xffffffffu, s,  j);
            float nsj = __shfl_sync(0xffffffffu, ns, j);
            float4 v = __ldg((const float4*)(x + (size_t)sj * D_IN) + lane);
            acc.x = fmaf(v.x, nsj, acc.x);
            acc.y = fmaf(v.y, nsj, acc.y);
            acc.z = fmaf(v.z, nsj, acc.z);
            acc.w = fmaf(v.w, nsj, acc.w);
        }
    }
    float nin = rsqrtf(fmaxf((float)cnt, 1.f));
    float vv[4] = {acc.x * nin, acc.y * nin, acc.z * nin, acc.w * nin};
    __nv_bfloat16 h[4], l[4];
#pragma unroll
    for (int q = 0; q < 4; q++) bfsplit(vv[q], h[q], l[q]);
    __nv_bfloat162* ph = (__nv_bfloat162*)(g_aggh + (size_t)w * KP1 + lane * 4);
    __nv_bfloat162* pl = (__nv_bfloat162*)(g_aggl + (size_t)w * KP1 + lane * 4);
    ph[0] = __halves2bfloat162(h[0], h[1]);
    ph[1] = __halves2bfloat162(h[2], h[3]);
    pl[0] = __halves2bfloat162(l[0], l[1]);
    pl[1] = __halves2bfloat162(l[2], l[3]);
}

// ---------------- weight prep (no counter zeroing; that lives in gemm3) ------
__global__ void prep_weights(const float* __restrict__ W1, const float* __restrict__ b1,
                             const float* __restrict__ Wn, const float* __restrict__ Ws,
                             const float* __restrict__ W3) {
    int stride = gridDim.x * blockDim.x;
    int t0 = blockIdx.x * blockDim.x + threadIdx.x;
    for (int i = t0; i < N1 * KP1; i += stride) {
        int n = i / KP1, k = i % KP1;
        float v = (n < D1) ? W1[k * D1 + n] : 0.f;
        bfsplit(v, g_w1h[i], g_w1l[i]);
    }
    for (int i = t0; i < N2 * KP2; i += stride) {
        int n = i / KP2, k = i % KP2;
        float v = 0.f;
        if (k < D1) {
            if (n < D2)                       v = Wn[k * D2 + n];
            else if (n >= PS && n < PS + D2)  v = Ws[k * D2 + (n - PS)];
        }
        bfsplit(v, g_w2h[i], g_w2l[i]);
    }
    for (int i = t0; i < N3 * KP3; i += stride) {
        int n = i / KP3, k = i % KP3;
        float v = (k < D2) ? W3[k * D_OUT + n] : 0.f;
        bfsplit(v, g_w3h[i], g_w3l[i]);
    }
    for (int i = t0; i < N1; i += stride) g_b1p[i] = (i < D1) ? b1[i] : 0.f;
}

// ---------------- GEMM1 (HMMA): h1 = ELU(agg @ W1 + b1) -> bf16 split --------
// grid (391, 2): 128 rows x 80 cols per block
__global__ __launch_bounds__(256) void hmma_gemm1_kernel() {
    __shared__ __nv_bfloat16 sm[2 * (256 + 2 * 80) * SMS];
    int wid = threadIdx.x >> 5;
    int lane = threadIdx.x & 31;
    int gid = lane >> 2, tig = lane & 3;
    int row0 = blockIdx.x * 128;
    int cb = blockIdx.y * 80;
    float acc[10][4];
#pragma unroll
    for (int i = 0; i < 10; i++)
#pragma unroll
        for (int j = 0; j < 4; j++) acc[i][j] = 0.f;
    hmma_tiles<10, 8, KP1, KP1, 80>(g_aggh, g_aggl, g_w1h, g_w1l, row0, cb, sm, acc);
    int r0 = row0 + wid * 16 + gid, r1 = r0 + 8;
#pragma unroll
    for (int nt = 0; nt < 10; nt++) {
        int c = cb + nt * 8 + tig * 2;
        float bb0 = g_b1p[c], bb1 = g_b1p[c + 1];
        if (r0 < N_NODES) {
            float x0 = elu(acc[nt][0] + bb0), x1 = elu(acc[nt][1] + bb1);
            __nv_bfloat16 h0, l0, h1, l1;
            bfsplit(x0, h0, l0); bfsplit(x1, h1, l1);
            *(__nv_bfloat162*)(g_h1h + (size_t)r0 * H1S + c) = __halves2bfloat162(h0, h1);
            *(__nv_bfloat162*)(g_h1l + (size_t)r0 * H1S + c) = __halves2bfloat162(l0, l1);
        }
        if (r1 < N_NODES) {
            float x0 = elu(acc[nt][2] + bb0), x1 = elu(acc[nt][3] + bb1);
            __nv_bfloat16 h0, l0, h1, l1;
            bfsplit(x0, h0, l0); bfsplit(x1, h1, l1);
            *(__nv_bfloat162*)(g_h1h + (size_t)r1 * H1S + c) = __halves2bfloat162(h0, h1);
            *(__nv_bfloat162*)(g_h1l + (size_t)r1 * H1S + c) = __halves2bfloat162(l0, l1);
        }
    }
}

// ---------------- GEMM2 (HMMA): [p|s] = h1 @ [Wn|Ws] -> fp32 -----------------
// grid (391, 2): 128 rows x 112 cols; y==0 -> p, y==1 -> s
__global__ __launch_bounds__(256) void hmma_gemm2_kernel() {
    __shared__ __nv_bfloat16 sm[2 * (256 + 2 * 112) * SMS];
    int wid = threadIdx.x >> 5;
    int lane = threadIdx.x & 31;
    int gid = lane >> 2, tig = lane & 3;
    int row0 = blockIdx.x * 128;
    int cb = blockIdx.y * 112;
    float acc[14][4];
#pragma unroll
    for (int i = 0; i < 14; i++)
#pragma unroll
        for (int j = 0; j < 4; j++) acc[i][j] = 0.f;
    hmma_tiles<14, 10, KP2, KP2, 112>(g_h1h, g_h1l, g_w2h, g_w2l, row0, cb, sm, acc);
    int r0 = row0 + wid * 16 + gid, r1 = r0 + 8;
    float* base = (blockIdx.y == 0) ? g_pf : g_sf;
#pragma unroll
    for (int nt = 0; nt < 14; nt++) {
        int c = nt * 8 + tig * 2;
        if (r0 < N_NODES) {
            float2 v; v.x = acc[nt][0]; v.y = acc[nt][1];
            *(float2*)(base + (size_t)r0 * PS + c) = v;
        }
        if (r1 < N_NODES) {
            float2 v; v.x = acc[nt][2]; v.y = acc[nt][3];
            *(float2*)(base + (size_t)r1 * PS + c) = v;
        }
    }
}

// ---------------- gather 2 + SAGE epilogue -> h2 bf16 split ------------------
__global__ void gather2_kernel(const float* __restrict__ b2) {
    int w    = (blockIdx.x * blockDim.x + threadIdx.x) >> 5;
    int lane = threadIdx.x & 31;
    if (w >= N_NODES) return;
    int beg = g_rowoff[w];
    int cnt = g_deg_save[w];
    bool act = lane < (D2 / 4);   // 25 data lanes
    float4 acc = make_float4(0.f, 0.f, 0.f, 0.f);
    for (int base = 0; base < cnt; base += 32) {
        int idx = base + lane;
        int s = (idx < cnt) ? g_csr[beg + idx] : 0;
        int m = min(32, cnt - base);
        for (int j = 0; j < m; j++) {
            int sj = __shfl_sync(0xffffffffu, s, j);
            if (act) {
                float4 v = __ldg((const float4*)(g_pf + (size_t)sj * PS) + lane);
                acc.x += v.x; acc.y += v.y; acc.z += v.z; acc.w += v.w;
            }
        }
    }
    float o[4] = {0.f, 0.f, 0.f, 0.f};
    if (act) {
        float invd = 1.f / fmaxf((float)cnt, 1.f);
        float4 sv = *(const float4*)(g_sf + (size_t)w * PS + lane * 4);
        float4 bv = *(const float4*)(b2 + lane * 4);
        o[0] = elu(acc.x * invd + sv.x + bv.x);
        o[1] = elu(acc.y * invd + sv.y + bv.y);
        o[2] = elu(acc.z * invd + sv.z + bv.z);
        o[3] = elu(acc.w * invd + sv.w + bv.w);
    }
    if (lane < H2S / 4) {   // 28 lanes cover 112 cols (zeros beyond col 100)
        __nv_bfloat16 h[4], l[4];
#pragma unroll
        for (int q = 0; q < 4; q++) bfsplit(o[q], h[q], l[q]);
        __nv_bfloat162* ph = (__nv_bfloat162*)(g_h2h + (size_t)w * H2S + lane * 4);
        __nv_bfloat162* pl = (__nv_bfloat162*)(g_h2l + (size_t)w * H2S + lane * 4);
        ph[0] = __halves2bfloat162(h[0], h[1]);
        ph[1] = __halves2bfloat162(h[2], h[3]);
        pl[0] = __halves2bfloat162(l[0], l[1]);
        pl[1] = __halves2bfloat162(l[2], l[3]);
    }
}

// ---------------- GEMM3 (HMMA): out = ELU(h2 @ W3 + b3) + counter re-zero ----
// grid (391): 128 rows x 64 cols
__global__ __launch_bounds__(256) void hmma_gemm3_kernel(const float* __restrict__ b3,
                                                         float* __restrict__ out) {
    __shared__ __nv_bfloat16 sm[2 * (256 + 2 * 64) * SMS];
    int wid = threadIdx.x >> 5;
    int lane = threadIdx.x & 31;
    int gid = lane >> 2, tig = lane & 3;
    int row0 = blockIdx.x * 128;
    float acc[8][4];
#pragma unroll
    for (int i = 0; i < 8; i++)
#pragma unroll
        for (int j = 0; j < 4; j++) acc[i][j] = 0.f;
    hmma_tiles<8, 7, KP3, KP3, 64>(g_h2h, g_h2l, g_w3h, g_w3l, row0, 0, sm, acc);
    int r0 = row0 + wid * 16 + gid, r1 = r0 + 8;
#pragma unroll
    for (int nt = 0; nt < 8; nt++) {
        int c = nt * 8 + tig * 2;
        float bb0 = b3[c], bb1 = b3[c + 1];
        if (r0 < N_NODES) {
            float2 v;
            v.x = elu(acc[nt][0] + bb0);
            v.y = elu(acc[nt][1] + bb1);
            *(float2*)(out + (size_t)r0 * D_OUT + c) = v;
        }
        if (r1 < N_NODES) {
            float2 v;
            v.x = elu(acc[nt][2] + bb0);
            v.y = elu(acc[nt][3] + bb1);
            *(float2*)(out + (size_t)r1 * D_OUT + c) = v;
        }
    }
    // restore the zero-counter invariant for the next launch/replay
    int zr = row0 + threadIdx.x;              // 256 threads span 128 rows x 2 arrays
    if (threadIdx.x < 128) {
        if (zr < N_NODES) g_deg_out_i[zr] = 0;
    } else {
        int zr2 = row0 + threadIdx.x - 128;
        if (zr2 < N_NODES) g_deg_in_i[zr2] = 0;
    }
    if (blockIdx.x == 0 && threadIdx.x == 0) g_total = 0;
}

// ---------------- launch -----------------------------------------------------
// Order puts gather1 at launch #4 so the fixed-index ncu capture profiles it.
extern "C" void kernel_launch(void* const* d_in, const int* in_sizes, int n_in,
                              void* d_out, int out_size) {
    const float* x   = (const float*)d_in[0];
    const int*   src = (const int*)d_in[1];
    const int*   dst = (const int*)d_in[2];
    const float* W1  = (const float*)d_in[3];
    const float* b1  = (const float*)d_in[4];
    const float* Wn  = (const float*)d_in[5];
    const float* Ws  = (const float*)d_in[6];
    const float* b2  = (const float*)d_in[7];
    const float* W3  = (const float*)d_in[8];
    const float* b3  = (const float*)d_in[9];
    float* out = (float*)d_out;

    const int EDGE_BLOCKS = (N_EDGES + 255) / 256;      // 3125
    const int WARP_BLOCKS = (N_NODES * 32 + 255) / 256; // 6250
    const int MMA_BLOCKS  = (N_NODES + 127) / 128;      // 391

    degree_kernel<<<EDGE_BLOCKS, 256>>>(src, dst);            // 1
    rowoff_kernel<<<(N_NODES + 255) / 256, 256>>>();          // 2
    bucket_kernel<<<EDGE_BLOCKS, 256>>>(src, dst);            // 3
    gather1_kernel<<<WARP_BLOCKS, 256>>>(x);                  // 4  <- profiled
    prep_weights<<<160, 256>>>(W1, b1, Wn, Ws, W3);           // 5
    hmma_gemm1_kernel<<<dim3(MMA_BLOCKS, 2), 256>>>();        // 6
    hmma_gemm2_kernel<<<dim3(MMA_BLOCKS, 2), 256>>>();        // 7
    gather2_kernel<<<WARP_BLOCKS, 256>>>(b2);                 // 8
    hmma_gemm3_kernel<<<MMA_BLOCKS, 256>>>(b3, out);          // 9 (re-zeroes counters)
}